// round 15
// baseline (speedup 1.0000x reference)
#include <cuda_runtime.h>

typedef unsigned long long ull;
typedef unsigned int uint;

// ---- f32x2 packed helpers (sm_100+) ----
__device__ __forceinline__ ull pack2(float lo, float hi) {
    ull r; asm("mov.b64 %0, {%1, %2};" : "=l"(r) : "f"(lo), "f"(hi)); return r;
}
__device__ __forceinline__ ull dup2(float v) {
    ull r; asm("mov.b64 %0, {%1, %1};" : "=l"(r) : "f"(v)); return r;
}
__device__ __forceinline__ float2 unpack2(ull v) {
    float2 r; asm("mov.b64 {%0, %1}, %2;" : "=f"(r.x), "=f"(r.y) : "l"(v)); return r;
}
__device__ __forceinline__ ull fma2_(ull a, ull b, ull c) {
    ull r; asm("fma.rn.f32x2 %0, %1, %2, %3;" : "=l"(r) : "l"(a), "l"(b), "l"(c)); return r;
}
__device__ __forceinline__ ull mul2_(ull a, ull b) {
    ull r; asm("mul.rn.f32x2 %0, %1, %2;" : "=l"(r) : "l"(a), "l"(b)); return r;
}
__device__ __forceinline__ ull add2_(ull a, ull b) {
    ull r; asm("add.rn.f32x2 %0, %1, %2;" : "=l"(r) : "l"(a), "l"(b)); return r;
}
__device__ __forceinline__ ull abs2_(ull a) {
    ull r; asm("and.b64 %0, %1, 0x7FFFFFFF7FFFFFFF;" : "=l"(r) : "l"(a)); return r;
}
__device__ __forceinline__ ull neg2_(ull a) {
    ull r; asm("xor.b64 %0, %1, 0x8000000080000000;" : "=l"(r) : "l"(a)); return r;
}

// packed tanh-GELU + leaky on pre-activation pair {ch0, ch1}.
// ONE f16x2 MUFU tanh per pair (was two scalar f32 tanh) — MUFU is the
// hypothesized chip-wide binder at ~53.5us.
__device__ __forceinline__ ull act2(ull ap) {
    const ull K0 = dup2(0.79788456080286536f);
    const ull KK = dup2(0.79788456080286536f * 0.044715f);
    const ull A2 = dup2(0.2525f);   // leaky(0.5z) = .2525 z + .2475 |z|
    const ull B2 = dup2(0.2475f);
    ull x2 = mul2_(ap, ap);
    ull u  = mul2_(ap, fma2_(x2, KK, K0));       // k0*a*(1 + k1*a^2)
    float2 uv = unpack2(u);
    uint uh;
    asm("cvt.rn.f16x2.f32 %0, %1, %2;" : "=r"(uh) : "f"(uv.y), "f"(uv.x));
    uint thh;
    asm("tanh.approx.f16x2 %0, %1;" : "=r"(thh) : "r"(uh));
    float t0, t1;
    asm("{\n\t.reg .b16 lo, hi;\n\tmov.b32 {lo, hi}, %2;\n\t"
        "cvt.f32.f16 %0, lo;\n\tcvt.f32.f16 %1, hi;\n\t}"
        : "=f"(t0), "=f"(t1) : "r"(thh));
    ull z = fma2_(ap, pack2(t0, t1), ap);        // a*(1+tanh) = 2*gelu
    return fma2_(z, A2, mul2_(abs2_(z), B2));
}

// Grid 8192 = (b, cin, half). CTA = half a row (1024 output pairs), 256 thr.
// No x staging: phase 1 reads its window straight from global (L1-cached);
// the phase-2 skip values ride in registers across the phase boundary.
// Static smem 16.5 KB: band arrays only, all hot accesses LDS/STS.128 CF.
//   LB[1032] : L pair m (local, [-3..1026]) at LB[m+4], {ch0,ch1} ull
//   HB[1028] : H pair m ([-1..1025]) at HB[m+2]
__global__ __launch_bounds__(256, 4)
void fused_block_wavelet_down(
    const float* __restrict__ x,      // (64, 64, 4096)
    const float* __restrict__ w1,     // (128, 1, 7)
    const float* __restrict__ g1,
    const float* __restrict__ b1,
    const float* __restrict__ m1,
    const float* __restrict__ v1,
    const float* __restrict__ w2L,    // (128, 1, 7)
    const float* __restrict__ w2H,    // (128, 1, 3)
    const float* __restrict__ wskip,  // (128, 1, 1)
    float* __restrict__ out)          // (64, 128, 4096)
{
    __shared__ __align__(16) ull LB[1032];
    __shared__ __align__(16) ull HB[1028];

    const int tid  = threadIdx.x;
    const int bx   = blockIdx.x;
    const int half = bx & 1;
    const int cin  = (bx >> 1) & 63;
    const int b    = bx >> 7;
    const int oc0  = 2 * cin;

    const float* xrow = x + ((size_t)(b * 64 + cin) << 12);   // full row
    const float4* xr4 = reinterpret_cast<const float4*>(xrow);

    // phase-1 weights, BN folded
    float wk0[7], wk1[7], bias0, bias1;
    {
        const float inv0 = g1[oc0]     * rsqrtf(v1[oc0]     + 1e-5f);
        const float inv1 = g1[oc0 + 1] * rsqrtf(v1[oc0 + 1] + 1e-5f);
        #pragma unroll
        for (int k = 0; k < 7; ++k) {
            wk0[k] = w1[oc0 * 7 + k]     * inv0;
            wk1[k] = w1[oc0 * 7 + 7 + k] * inv1;
        }
        bias0 = b1[oc0]     - m1[oc0]     * inv0;
        bias1 = b1[oc0 + 1] - m1[oc0 + 1] * inv1;
    }

    float4 skreg[2];   // x(4tp..4tp+3) per iter — phase-2 skip values

    // ---- phase 1: conv7(+BN) + GELU + leaky + Haar, pairs 2tp, 2tp+1 ----
    {
        #pragma unroll
        for (int p = 0; p < 2; ++p) {
            const int tp = tid + p * 256;             // 0..511
            const int g1i = half * 512 + tp;          // center float4 idx
            const float4 z4 = make_float4(0, 0, 0, 0);
            float4 f0 = (g1i - 1 >= 0)   ? xr4[g1i - 1] : z4;
            float4 f1 = xr4[g1i];
            float4 f2 = (g1i + 1 <= 1023) ? xr4[g1i + 1] : z4;
            skreg[p] = f1;

            float v[12] = {f0.x,f0.y,f0.z,f0.w, f1.x,f1.y,f1.z,f1.w,
                           f2.x,f2.y,f2.z,f2.w};      // v[i] = x_loc(4tp-4+i)
            ull hp[4];
            #pragma unroll
            for (int j = 0; j < 4; ++j) {
                float a0 = bias0, a1 = bias1;
                #pragma unroll
                for (int k = 0; k < 7; ++k) {
                    a0 = fmaf(v[1 + j + k], wk0[k], a0);
                    a1 = fmaf(v[1 + j + k], wk1[k], a1);
                }
                hp[j] = act2(pack2(a0, a1));
            }
            *reinterpret_cast<ulonglong2*>(LB + 2 * tp + 4) = make_ulonglong2(
                add2_(hp[0], hp[1]), add2_(hp[2], hp[3]));
            *reinterpret_cast<ulonglong2*>(HB + 2 * tp + 2) = make_ulonglong2(
                add2_(hp[0], neg2_(hp[1])), add2_(hp[2], neg2_(hp[3])));
        }

        // seam/edge pairs: threads 0..5 -> L m = -3,-2,-1,1024,1025,1026
        // (H for m = -1,1024,1025). True row edges store zeros (conv2 pad).
        if (tid < 6) {
            const int m = (tid < 3) ? (tid - 3) : (1021 + tid);
            const bool zero = half ? (tid >= 3) : (tid < 3);
            ull Lp = 0, Hp = 0;
            if (!zero) {
                // h(2m), h(2m+1); x global t = half*2048 + 2m - 3 + k (valid)
                const float* xg = xrow + half * 2048 + 2 * m - 3;
                float a0 = bias0, a1 = bias1, c0 = bias0, c1 = bias1;
                #pragma unroll
                for (int k = 0; k < 7; ++k) {
                    const float xe = xg[k];
                    const float xo = xg[k + 1];
                    a0 = fmaf(xe, wk0[k], a0);
                    a1 = fmaf(xe, wk1[k], a1);
                    c0 = fmaf(xo, wk0[k], c0);
                    c1 = fmaf(xo, wk1[k], c1);
                }
                ull h0 = act2(pack2(a0, a1));
                ull h1 = act2(pack2(c0, c1));
                Lp = add2_(h0, h1);
                Hp = add2_(h0, neg2_(h1));
            }
            LB[m + 4] = Lp;
            if (tid >= 2 && tid <= 4) HB[m + 2] = Hp;
        }
    }

    // phase-2 weights packed per channel pair; 1/sqrt2 folded (w/2)
    ull wLp[7], wHp[3], wsp;
    #pragma unroll
    for (int k = 0; k < 7; ++k)
        wLp[k] = pack2(w2L[oc0 * 7 + k] * 0.5f, w2L[oc0 * 7 + 7 + k] * 0.5f);
    #pragma unroll
    for (int k = 0; k < 3; ++k)
        wHp[k] = pack2(w2H[oc0 * 3 + k] * 0.5f, w2H[oc0 * 3 + 3 + k] * 0.5f);
    wsp = pack2(wskip[oc0], wskip[oc0 + 1]);

    const ull A1 = dup2(0.505f);    // leaky(o) = .505 o + .495 |o|
    const ull B1 = dup2(0.495f);

    __syncthreads();

    // ---- phase 2: conv7L/conv3H + merge + skip(regs) + leaky ----
    {
        const ulonglong2* LA = reinterpret_cast<const ulonglong2*>(LB) + tid;
        const ulonglong2* HA = reinterpret_cast<const ulonglong2*>(HB) + tid;
        float4* o0p = reinterpret_cast<float4*>(
            out + ((size_t)(b * 128 + oc0) << 12)) + half * 512 + tid;

        #pragma unroll
        for (int p = 0; p < 2; ++p) {
            // lp[i] = LB[2tp+i] = L pair (2tp+i-4); consume i = 1..8
            ulonglong2 q0 = LA[0], q1 = LA[1], q2 = LA[2], q3 = LA[3], q4 = LA[4];
            ull lp[10] = {q0.x,q0.y, q1.x,q1.y, q2.x,q2.y, q3.x,q3.y, q4.x,q4.y};
            ull yLA = mul2_(wLp[0], lp[1]);
            ull yLB = mul2_(wLp[0], lp[2]);
            #pragma unroll
            for (int j = 1; j < 7; ++j) {
                yLA = fma2_(wLp[j], lp[1 + j], yLA);
                yLB = fma2_(wLp[j], lp[2 + j], yLB);
            }

            // hq[i] = HB[2tp+i] = H pair (2tp+i-2); consume i = 1..4
            ulonglong2 h0 = HA[0], h1 = HA[1], h2 = HA[2];
            ull hq[6] = {h0.x,h0.y, h1.x,h1.y, h2.x,h2.y};
            ull zA = mul2_(wHp[0], hq[1]);
            ull zB = mul2_(wHp[0], hq[2]);
            #pragma unroll
            for (int j = 1; j < 3; ++j) {
                zA = fma2_(wHp[j], hq[1 + j], zA);
                zB = fma2_(wHp[j], hq[2 + j], zB);
            }

            const float4 sk = skreg[p];             // x_loc(4tp .. 4tp+3)
            ull eA = add2_(yLA, zA), dA = add2_(yLA, neg2_(zA));
            ull eB = add2_(yLB, zB), dB = add2_(yLB, neg2_(zB));
            eA = fma2_(dup2(sk.x), wsp, eA);
            dA = fma2_(dup2(sk.y), wsp, dA);
            eB = fma2_(dup2(sk.z), wsp, eB);
            dB = fma2_(dup2(sk.w), wsp, dB);
            eA = fma2_(eA, A1, mul2_(abs2_(eA), B1));
            dA = fma2_(dA, A1, mul2_(abs2_(dA), B1));
            eB = fma2_(eB, A1, mul2_(abs2_(eB), B1));
            dB = fma2_(dB, A1, mul2_(abs2_(dB), B1));

            float2 ea = unpack2(eA), da = unpack2(dA);
            float2 eb = unpack2(eB), db = unpack2(dB);
            o0p[0]    = make_float4(ea.x, da.x, eb.x, db.x);
            o0p[1024] = make_float4(ea.y, da.y, eb.y, db.y);   // channel 1 row

            LA += 256; HA += 256; o0p += 256;
        }
    }
}

extern "C" void kernel_launch(void* const* d_in, const int* in_sizes, int n_in,
                              void* d_out, int out_size) {
    const float* x     = (const float*)d_in[0];
    const float* w1    = (const float*)d_in[1];
    const float* g1    = (const float*)d_in[2];
    const float* b1    = (const float*)d_in[3];
    const float* m1    = (const float*)d_in[4];
    const float* v1    = (const float*)d_in[5];
    const float* w2L   = (const float*)d_in[6];
    const float* w2H   = (const float*)d_in[7];
    const float* wskip = (const float*)d_in[8];
    float* out = (float*)d_out;

    fused_block_wavelet_down<<<64 * 64 * 2, 256>>>(
        x, w1, g1, b1, m1, v1, w2L, w2H, wskip, out);
}

// round 16
// speedup vs baseline: 1.0304x; 1.0304x over previous
#include <cuda_runtime.h>

typedef unsigned long long ull;

// ---- f32x2 packed helpers (sm_100+) ----
__device__ __forceinline__ ull pack2(float lo, float hi) {
    ull r; asm("mov.b64 %0, {%1, %2};" : "=l"(r) : "f"(lo), "f"(hi)); return r;
}
__device__ __forceinline__ ull dup2(float v) {
    ull r; asm("mov.b64 %0, {%1, %1};" : "=l"(r) : "f"(v)); return r;
}
__device__ __forceinline__ float2 unpack2(ull v) {
    float2 r; asm("mov.b64 {%0, %1}, %2;" : "=f"(r.x), "=f"(r.y) : "l"(v)); return r;
}
__device__ __forceinline__ ull fma2_(ull a, ull b, ull c) {
    ull r; asm("fma.rn.f32x2 %0, %1, %2, %3;" : "=l"(r) : "l"(a), "l"(b), "l"(c)); return r;
}
__device__ __forceinline__ ull mul2_(ull a, ull b) {
    ull r; asm("mul.rn.f32x2 %0, %1, %2;" : "=l"(r) : "l"(a), "l"(b)); return r;
}
__device__ __forceinline__ ull add2_(ull a, ull b) {
    ull r; asm("add.rn.f32x2 %0, %1, %2;" : "=l"(r) : "l"(a), "l"(b)); return r;
}
__device__ __forceinline__ ull abs2_(ull a) {
    ull r; asm("and.b64 %0, %1, 0x7FFFFFFF7FFFFFFF;" : "=l"(r) : "l"(a)); return r;
}
__device__ __forceinline__ ull neg2_(ull a) {
    ull r; asm("xor.b64 %0, %1, 0x8000000080000000;" : "=l"(r) : "l"(a)); return r;
}
__device__ __forceinline__ float tanh_approx(float x) {
    float y; asm("tanh.approx.f32 %0, %1;" : "=f"(y) : "f"(x)); return y;
}

// packed tanh-GELU + leaky on pre-activation pair {ch0, ch1} (round-7 math)
__device__ __forceinline__ ull act2(ull ap) {
    const ull K0 = dup2(0.79788456080286536f);
    const ull KK = dup2(0.79788456080286536f * 0.044715f);
    const ull A2 = dup2(0.2525f);   // leaky(0.5z) = .2525 z + .2475 |z|
    const ull B2 = dup2(0.2475f);
    ull x2 = mul2_(ap, ap);
    ull u  = mul2_(ap, fma2_(x2, KK, K0));       // k0*a*(1 + k1*a^2)
    float2 uv = unpack2(u);
    ull th = pack2(tanh_approx(uv.x), tanh_approx(uv.y));
    ull z  = fma2_(ap, th, ap);                  // a*(1+tanh) = 2*gelu
    return fma2_(z, A2, mul2_(abs2_(z), B2));
}

// One CTA per (b, cin) FULL row (round-7 structure: 4 iters/phase), but with
// no x staging — phase 1's window and phase 2's skip read straight from
// global (row fits L1). Interleaved {ch0,ch1} ull bands; every hot shared
// access is a conflict-free 16B-stride LDS/STS.128.
//   LB[2056] : L pair m at LB[m+4], m in [-3..2050]; zeros at [0..3],[2052..2055]
//   HB[2052] : H pair m at HB[m+2], m in [-2..2049]; zeros at [0..1],[2050..2051]
__global__ __launch_bounds__(256, 4)
void fused_block_wavelet_down(
    const float* __restrict__ x,      // (64, 64, 4096)
    const float* __restrict__ w1,     // (128, 1, 7)
    const float* __restrict__ g1,
    const float* __restrict__ b1,
    const float* __restrict__ m1,
    const float* __restrict__ v1,
    const float* __restrict__ w2L,    // (128, 1, 7)
    const float* __restrict__ w2H,    // (128, 1, 3)
    const float* __restrict__ wskip,  // (128, 1, 1)
    float* __restrict__ out)          // (64, 128, 4096)
{
    __shared__ __align__(16) ull LB[2056];
    __shared__ __align__(16) ull HB[2052];

    const int tid = threadIdx.x;
    const int b   = blockIdx.x >> 6;
    const int cin = blockIdx.x & 63;
    const int oc0 = 2 * cin;

    const float4* xr4 = reinterpret_cast<const float4*>(
        x + ((size_t)(b * 64 + cin) << 12));

    // zero band pad cells (exact ull2 slots; never overlap real data)
    if (tid == 0) {
        *reinterpret_cast<ulonglong2*>(LB)     = make_ulonglong2(0, 0);
        *reinterpret_cast<ulonglong2*>(LB + 2) = make_ulonglong2(0, 0);
    } else if (tid == 1) {
        *reinterpret_cast<ulonglong2*>(LB + 2052) = make_ulonglong2(0, 0);
        *reinterpret_cast<ulonglong2*>(LB + 2054) = make_ulonglong2(0, 0);
    } else if (tid == 2) {
        *reinterpret_cast<ulonglong2*>(HB)        = make_ulonglong2(0, 0);
        *reinterpret_cast<ulonglong2*>(HB + 2050) = make_ulonglong2(0, 0);
    }

    // phase-1 weights, BN folded
    float wk0[7], wk1[7], bias0, bias1;
    {
        const float inv0 = g1[oc0]     * rsqrtf(v1[oc0]     + 1e-5f);
        const float inv1 = g1[oc0 + 1] * rsqrtf(v1[oc0 + 1] + 1e-5f);
        #pragma unroll
        for (int k = 0; k < 7; ++k) {
            wk0[k] = w1[oc0 * 7 + k]     * inv0;
            wk1[k] = w1[oc0 * 7 + 7 + k] * inv1;
        }
        bias0 = b1[oc0]     - m1[oc0]     * inv0;
        bias1 = b1[oc0 + 1] - m1[oc0 + 1] * inv1;
    }

    // ---- phase 1: conv7(+BN) + GELU + leaky + Haar, pairs 2tp, 2tp+1 ----
    {
        #pragma unroll 1
        for (int p = 0; p < 4; ++p) {
            const int tp = tid + p * 256;              // 0..1023
            const float4 z4 = make_float4(0, 0, 0, 0);
            float4 f0 = (tp >= 1)    ? xr4[tp - 1] : z4;   // x[4tp-4..4tp-1]
            float4 f1 = xr4[tp];                           // x[4tp  ..4tp+3]
            float4 f2 = (tp <= 1022) ? xr4[tp + 1] : z4;   // x[4tp+4..4tp+7]

            float v[12] = {f0.x,f0.y,f0.z,f0.w, f1.x,f1.y,f1.z,f1.w,
                           f2.x,f2.y,f2.z,f2.w};       // v[i] = x[4tp-4+i]
            ull hp[4];
            #pragma unroll
            for (int j = 0; j < 4; ++j) {
                float a0 = bias0, a1 = bias1;
                #pragma unroll
                for (int k = 0; k < 7; ++k) {
                    a0 = fmaf(v[1 + j + k], wk0[k], a0);
                    a1 = fmaf(v[1 + j + k], wk1[k], a1);
                }
                hp[j] = act2(pack2(a0, a1));
            }
            // pairs 2tp (h 4tp,4tp+1) and 2tp+1 (h 4tp+2,4tp+3)
            *reinterpret_cast<ulonglong2*>(LB + 2 * tp + 4) = make_ulonglong2(
                add2_(hp[0], hp[1]), add2_(hp[2], hp[3]));
            *reinterpret_cast<ulonglong2*>(HB + 2 * tp + 2) = make_ulonglong2(
                add2_(hp[0], neg2_(hp[1])), add2_(hp[2], neg2_(hp[3])));
        }
    }

    // phase-2 weights packed per channel pair; 1/sqrt2 folded (w/2)
    ull wLp[7], wHp[3], wsp;
    #pragma unroll
    for (int k = 0; k < 7; ++k)
        wLp[k] = pack2(w2L[oc0 * 7 + k] * 0.5f, w2L[oc0 * 7 + 7 + k] * 0.5f);
    #pragma unroll
    for (int k = 0; k < 3; ++k)
        wHp[k] = pack2(w2H[oc0 * 3 + k] * 0.5f, w2H[oc0 * 3 + 3 + k] * 0.5f);
    wsp = pack2(wskip[oc0], wskip[oc0 + 1]);

    const ull A1 = dup2(0.505f);    // leaky(o) = .505 o + .495 |o|
    const ull B1 = dup2(0.495f);

    __syncthreads();

    // ---- phase 2: conv7L/conv3H + merge + skip(L1 reload) + leaky ----
    {
        const ulonglong2* LA = reinterpret_cast<const ulonglong2*>(LB) + tid;
        const ulonglong2* HA = reinterpret_cast<const ulonglong2*>(HB) + tid;
        const float4* skp = xr4 + tid;
        float4* o0p = reinterpret_cast<float4*>(
            out + ((size_t)(b * 128 + oc0) << 12)) + tid;

        #pragma unroll 1
        for (int p = 0; p < 4; ++p) {
            // lp[i] = LB[2tp+i] = L pair (2tp+i-4); consume i = 1..8
            ulonglong2 q0 = LA[0], q1 = LA[1], q2 = LA[2], q3 = LA[3], q4 = LA[4];
            ull lp[10] = {q0.x,q0.y, q1.x,q1.y, q2.x,q2.y, q3.x,q3.y, q4.x,q4.y};
            ull yLA = mul2_(wLp[0], lp[1]);
            ull yLB = mul2_(wLp[0], lp[2]);
            #pragma unroll
            for (int j = 1; j < 7; ++j) {
                yLA = fma2_(wLp[j], lp[1 + j], yLA);
                yLB = fma2_(wLp[j], lp[2 + j], yLB);
            }

            // hq[i] = HB[2tp+i] = H pair (2tp+i-2); consume i = 1..4
            ulonglong2 h0 = HA[0], h1 = HA[1], h2 = HA[2];
            ull hq[6] = {h0.x,h0.y, h1.x,h1.y, h2.x,h2.y};
            ull zA = mul2_(wHp[0], hq[1]);
            ull zB = mul2_(wHp[0], hq[2]);
            #pragma unroll
            for (int j = 1; j < 3; ++j) {
                zA = fma2_(wHp[j], hq[1 + j], zA);
                zB = fma2_(wHp[j], hq[2 + j], zB);
            }

            const float4 sk = skp[0];               // x[4tp..4tp+3], L1 hit
            ull eA = add2_(yLA, zA), dA = add2_(yLA, neg2_(zA));
            ull eB = add2_(yLB, zB), dB = add2_(yLB, neg2_(zB));
            eA = fma2_(dup2(sk.x), wsp, eA);
            dA = fma2_(dup2(sk.y), wsp, dA);
            eB = fma2_(dup2(sk.z), wsp, eB);
            dB = fma2_(dup2(sk.w), wsp, dB);
            eA = fma2_(eA, A1, mul2_(abs2_(eA), B1));
            dA = fma2_(dA, A1, mul2_(abs2_(dA), B1));
            eB = fma2_(eB, A1, mul2_(abs2_(eB), B1));
            dB = fma2_(dB, A1, mul2_(abs2_(dB), B1));

            float2 ea = unpack2(eA), da = unpack2(dA);
            float2 eb = unpack2(eB), db = unpack2(dB);
            o0p[0]    = make_float4(ea.x, da.x, eb.x, db.x);
            o0p[1024] = make_float4(ea.y, da.y, eb.y, db.y);   // channel 1 row

            LA += 256; HA += 256; skp += 256; o0p += 256;
        }
    }
}

extern "C" void kernel_launch(void* const* d_in, const int* in_sizes, int n_in,
                              void* d_out, int out_size) {
    const float* x     = (const float*)d_in[0];
    const float* w1    = (const float*)d_in[1];
    const float* g1    = (const float*)d_in[2];
    const float* b1    = (const float*)d_in[3];
    const float* m1    = (const float*)d_in[4];
    const float* v1    = (const float*)d_in[5];
    const float* w2L   = (const float*)d_in[6];
    const float* w2H   = (const float*)d_in[7];
    const float* wskip = (const float*)d_in[8];
    float* out = (float*)d_out;

    fused_block_wavelet_down<<<64 * 64, 256>>>(
        x, w1, g1, b1, m1, v1, w2L, w2H, wskip, out);
}

// round 17
// speedup vs baseline: 1.0742x; 1.0425x over previous
#include <cuda_runtime.h>
#include <cuda_bf16.h>

// Dynamic smem layout (floats):
//   sx  @ 0    len 4104 : x[t] at sx[t+4]; zeros [0..3], [4100..4103]
//   sLI @ 4104 len 4112 : pair i of {ch0,ch1} at float2 idx i+4 (ull2 idx: pair2T at T+2)
//                         zeros float2 idx 0..3 and 2052..2055
//   sHI @ 8216 len 4112 : pair i at float2 idx i+2; zeros idx 0..1 and 2050..2055
// total 12328 floats = 49312 bytes
#define SMEM_FLOATS 12328

typedef unsigned long long ull;

// ---- f32x2 packed helpers (sm_100+) ----
__device__ __forceinline__ ull pack2(float lo, float hi) {
    ull r; asm("mov.b64 %0, {%1, %2};" : "=l"(r) : "f"(lo), "f"(hi)); return r;
}
__device__ __forceinline__ float2 unpack2(ull v) {
    float2 r; asm("mov.b64 {%0, %1}, %2;" : "=f"(r.x), "=f"(r.y) : "l"(v)); return r;
}
__device__ __forceinline__ ull fma2_(ull a, ull b, ull c) {
    ull r; asm("fma.rn.f32x2 %0, %1, %2, %3;" : "=l"(r) : "l"(a), "l"(b), "l"(c)); return r;
}
__device__ __forceinline__ ull mul2_(ull a, ull b) {
    ull r; asm("mul.rn.f32x2 %0, %1, %2;" : "=l"(r) : "l"(a), "l"(b)); return r;
}
__device__ __forceinline__ ull add2_(ull a, ull b) {
    ull r; asm("add.rn.f32x2 %0, %1, %2;" : "=l"(r) : "l"(a), "l"(b)); return r;
}
__device__ __forceinline__ ull abs2_(ull a) {
    ull r; asm("and.b64 %0, %1, 0x7FFFFFFF7FFFFFFF;" : "=l"(r) : "l"(a)); return r;
}
__device__ __forceinline__ ull neg2_(ull a) {
    ull r; asm("xor.b64 %0, %1, 0x8000000080000000;" : "=l"(r) : "l"(a)); return r;
}
__device__ __forceinline__ float tanh_approx(float x) {
    float y; asm("tanh.approx.f32 %0, %1;" : "=f"(y) : "f"(x)); return y;
}

// One CTA per (b, cin); produces output channels 2*cin, 2*cin+1.
// BN folded into w1; 1/sqrt2 Haar factors folded into w2L/w2H (=> w/2).
// Channel-interleaved Haar bands in smem; phase 2 fully f32x2.
__global__ __launch_bounds__(256, 4)
void fused_block_wavelet_down(
    const float* __restrict__ x,      // (64, 64, 4096)
    const float* __restrict__ w1,     // (128, 1, 7)
    const float* __restrict__ g1,
    const float* __restrict__ b1,
    const float* __restrict__ m1,
    const float* __restrict__ v1,
    const float* __restrict__ w2L,    // (128, 1, 7)
    const float* __restrict__ w2H,    // (128, 1, 3)
    const float* __restrict__ wskip,  // (128, 1, 1)
    float* __restrict__ out)          // (64, 128, 4096)
{
    extern __shared__ float smem[];
    float* sx  = smem;
    float* sLI = smem + 4104;
    float* sHI = smem + 8216;

    const int tid = threadIdx.x;
    const int b   = blockIdx.x >> 6;
    const int cin = blockIdx.x & 63;
    const int oc0 = 2 * cin;

    // zero pad cells (exact float4 slots; never overlap real data)
    if (tid == 0) *reinterpret_cast<float4*>(sx)          = make_float4(0,0,0,0);
    if (tid == 1) *reinterpret_cast<float4*>(sx + 4100)   = make_float4(0,0,0,0);
    if (tid == 2) *reinterpret_cast<float4*>(sLI)         = make_float4(0,0,0,0);
    if (tid == 3) *reinterpret_cast<float4*>(sLI + 4)     = make_float4(0,0,0,0);
    if (tid == 4) *reinterpret_cast<float4*>(sLI + 4104)  = make_float4(0,0,0,0);
    if (tid == 5) *reinterpret_cast<float4*>(sLI + 4108)  = make_float4(0,0,0,0);
    if (tid == 6) *reinterpret_cast<float4*>(sHI)         = make_float4(0,0,0,0);
    if (tid == 7) *reinterpret_cast<float4*>(sHI + 4100)  = make_float4(0,0,0,0);
    if (tid == 8) *reinterpret_cast<float4*>(sHI + 4104)  = make_float4(0,0,0,0);
    if (tid == 9) *reinterpret_cast<float4*>(sHI + 4108)  = make_float4(0,0,0,0);

    // load x row: LDG.128 -> STS.128, lane-contiguous
    {
        const float4* x4 = reinterpret_cast<const float4*>(
            x + ((size_t)(b * 64 + cin) << 12));
        float4* sxw = reinterpret_cast<float4*>(sx + 4);
        #pragma unroll
        for (int p = 0; p < 4; ++p)
            sxw[tid + p * 256] = x4[tid + p * 256];
    }

    // phase-1 weights, BN folded: h = conv(x, w1*inv) + bias
    float wk0[7], wk1[7], bias0, bias1;
    {
        const float inv0 = g1[oc0]     * rsqrtf(v1[oc0]     + 1e-5f);
        const float inv1 = g1[oc0 + 1] * rsqrtf(v1[oc0 + 1] + 1e-5f);
        #pragma unroll
        for (int k = 0; k < 7; ++k) {
            wk0[k] = w1[oc0 * 7 + k]     * inv0;
            wk1[k] = w1[oc0 * 7 + 7 + k] * inv1;
        }
        bias0 = b1[oc0]     - m1[oc0]     * inv0;
        bias1 = b1[oc0 + 1] - m1[oc0 + 1] * inv1;
    }

    // packed activation constants
    const ull C_HALF = pack2(0.5f, 0.5f);
    const ull C_K0   = pack2(0.79788456080286536f, 0.79788456080286536f);
    const ull C_KK   = pack2(0.79788456080286536f * 0.044715f,
                             0.79788456080286536f * 0.044715f);
    const ull C_A    = pack2(0.505f, 0.505f);   // leaky = .505g + .495|g|
    const ull C_B    = pack2(0.495f, 0.495f);

    __syncthreads();

    // ---- phase 1: scalar conv7(+BN), packed GELU+leaky, packed Haar ----
    {
        const float4* sxp = reinterpret_cast<const float4*>(sx) + tid;
        ulonglong2* sLw = reinterpret_cast<ulonglong2*>(sLI) + tid + 2;
        ulonglong2* sHw = reinterpret_cast<ulonglong2*>(sHI) + tid + 1;

        #pragma unroll 1
        for (int p = 0; p < 4; ++p) {
            float4 f0 = sxp[0];                 // conflict-free, lane-contiguous
            float4 f1 = sxp[1];
            float4 f2 = sxp[2];
            float v[12] = {f0.x,f0.y,f0.z,f0.w, f1.x,f1.y,f1.z,f1.w,
                           f2.x,f2.y,f2.z,f2.w};

            ull hp[4];
            #pragma unroll
            for (int j = 0; j < 4; ++j) {
                float a0 = bias0, a1 = bias1;
                #pragma unroll
                for (int k = 0; k < 7; ++k) {
                    a0 = fmaf(v[1 + j + k], wk0[k], a0);
                    a1 = fmaf(v[1 + j + k], wk1[k], a1);
                }
                // packed tanh-GELU + leaky on {a0, a1}
                ull ap = pack2(a0, a1);
                ull t  = mul2_(ap, C_HALF);                 // 0.5a
                ull x2 = mul2_(ap, ap);                     // a^2
                ull u  = mul2_(ap, fma2_(x2, C_KK, C_K0));  // k0*a*(1+k1*a^2)
                float2 uv = unpack2(u);
                ull th = pack2(tanh_approx(uv.x), tanh_approx(uv.y));
                ull g  = fma2_(t, th, t);                   // 0.5a(1+tanh)
                hp[j]  = fma2_(g, C_A, mul2_(abs2_(g), C_B));
            }

            // packed Haar, channel-interleaved stores (STS.128)
            ull sLa = add2_(hp[0], hp[1]);
            ull sHa = add2_(hp[0], neg2_(hp[1]));
            ull sLb = add2_(hp[2], hp[3]);
            ull sHb = add2_(hp[2], neg2_(hp[3]));
            sLw[0] = make_ulonglong2(sLa, sLb);   // pairs 2T, 2T+1
            sHw[0] = make_ulonglong2(sHa, sHb);

            sxp += 256; sLw += 256; sHw += 256;
        }
    }

    // phase-2 weights, packed per channel-pair; 1/sqrt2 folded (w/2)
    ull wLp[7], wHp[3], wsp;
    #pragma unroll
    for (int k = 0; k < 7; ++k)
        wLp[k] = pack2(w2L[oc0 * 7 + k] * 0.5f, w2L[oc0 * 7 + 7 + k] * 0.5f);
    #pragma unroll
    for (int k = 0; k < 3; ++k)
        wHp[k] = pack2(w2H[oc0 * 3 + k] * 0.5f, w2H[oc0 * 3 + 3 + k] * 0.5f);
    wsp = pack2(wskip[oc0], wskip[oc0 + 1]);

    __syncthreads();

    // ---- phase 2: packed conv7L/conv3H + merge + skip + leaky ----
    {
        const ulonglong2* Lq = reinterpret_cast<const ulonglong2*>(sLI) + tid;
        const ulonglong2* Hq = reinterpret_cast<const ulonglong2*>(sHI) + tid;
        const float4* skp = reinterpret_cast<const float4*>(sx) + tid + 1;
        float4* o0p = reinterpret_cast<float4*>(
            out + ((size_t)(b * 128 + oc0) << 12)) + tid;
        float4* o1p = o0p + 1024;              // next channel row = 4096 floats

        #pragma unroll 1
        for (int p = 0; p < 4; ++p) {
            // L window: pairs 2tp-4 .. 2tp+5 (10 packed), 5 LDS.128 CF
            ull lp[10];
            #pragma unroll
            for (int c = 0; c < 5; ++c) {
                ulonglong2 q = Lq[c];
                lp[2 * c] = q.x; lp[2 * c + 1] = q.y;
            }
            ull yLA = mul2_(wLp[0], lp[1]);     // pair A = 2tp, window pairs -3..+3
            ull yLB = mul2_(wLp[0], lp[2]);     // pair B = 2tp+1
            #pragma unroll
            for (int j = 1; j < 7; ++j) {
                yLA = fma2_(wLp[j], lp[1 + j], yLA);
                yLB = fma2_(wLp[j], lp[2 + j], yLB);
            }

            // H window: pairs 2tp-2 .. 2tp+3 (6 packed), 3 LDS.128 CF
            ull hq[6];
            #pragma unroll
            for (int c = 0; c < 3; ++c) {
                ulonglong2 q = Hq[c];
                hq[2 * c] = q.x; hq[2 * c + 1] = q.y;
            }
            ull yHA = mul2_(wHp[0], hq[1]);
            ull yHB = mul2_(wHp[0], hq[2]);
            #pragma unroll
            for (int j = 1; j < 3; ++j) {
                yHA = fma2_(wHp[j], hq[1 + j], yHA);
                yHB = fma2_(wHp[j], hq[2 + j], yHB);
            }

            const float4 sk = skp[0];           // x[4tp..4tp+3]
            ull eA = add2_(yLA, yHA), dA = add2_(yLA, neg2_(yHA));
            ull eB = add2_(yLB, yHB), dB = add2_(yLB, neg2_(yHB));
            eA = fma2_(pack2(sk.x, sk.x), wsp, eA);
            dA = fma2_(pack2(sk.y, sk.y), wsp, dA);
            eB = fma2_(pack2(sk.z, sk.z), wsp, eB);
            dB = fma2_(pack2(sk.w, sk.w), wsp, dB);
            eA = fma2_(eA, C_A, mul2_(abs2_(eA), C_B));
            dA = fma2_(dA, C_A, mul2_(abs2_(dA), C_B));
            eB = fma2_(eB, C_A, mul2_(abs2_(eB), C_B));
            dB = fma2_(dB, C_A, mul2_(abs2_(dB), C_B));

            float2 ea = unpack2(eA), da = unpack2(dA);
            float2 eb = unpack2(eB), db = unpack2(dB);
            o0p[0] = make_float4(ea.x, da.x, eb.x, db.x);
            o1p[0] = make_float4(ea.y, da.y, eb.y, db.y);

            Lq += 256; Hq += 256; skp += 256;
            o0p += 256; o1p += 256;
        }
    }
}

extern "C" void kernel_launch(void* const* d_in, const int* in_sizes, int n_in,
                              void* d_out, int out_size) {
    const float* x     = (const float*)d_in[0];
    const float* w1    = (const float*)d_in[1];
    const float* g1    = (const float*)d_in[2];
    const float* b1    = (const float*)d_in[3];
    const float* m1    = (const float*)d_in[4];
    const float* v1    = (const float*)d_in[5];
    const float* w2L   = (const float*)d_in[6];
    const float* w2H   = (const float*)d_in[7];
    const float* wskip = (const float*)d_in[8];
    float* out = (float*)d_out;

    const int smem_bytes = SMEM_FLOATS * (int)sizeof(float);
    static bool attr_set = false;
    if (!attr_set) {
        cudaFuncSetAttribute(fused_block_wavelet_down,
                             cudaFuncAttributeMaxDynamicSharedMemorySize,
                             smem_bytes);
        attr_set = true;
    }
    fused_block_wavelet_down<<<64 * 64, 256, smem_bytes>>>(
        x, w1, g1, b1, m1, v1, w2L, w2H, wskip, out);
}